// round 15
// baseline (speedup 1.0000x reference)
#include <cuda_runtime.h>
#include <math.h>

#define D        4096
#define KSEL     614              // int(4096 * 0.15)
#define THREADS  256
#define V4PT     4                // float4 per thread
#define SEG      128              // window candidates per warp (lambda~64, 8.5 sigma)
#define TSEG     16               // top-2 candidates per warp  (lambda~3.2, 7 sigma)
#define WLO      0.875f           // window lo  (k-th value = 1.036 +- 0.024)
#define WHI      1.5f             // window hi
#define TLO      2.5f             // top-2 gather floor
#define WLOBITS  0x3F600000u      // bits of 0.875f
#define FULL     0xFFFFFFFFu
#define GAIN     3.0f
#define NEG_INF  (-__int_as_float(0x7F800000))

// monotone float <-> uint mapping (slow path only)
__device__ __forceinline__ unsigned f2s(unsigned u) {
    return u ^ ((u & 0x80000000u) ? 0xFFFFFFFFu : 0x80000000u);
}
__device__ __forceinline__ float s2f(unsigned s) {
    unsigned u = (s & 0x80000000u) ? (s ^ 0x80000000u) : ~s;
    return __uint_as_float(u);
}

__global__ void __launch_bounds__(THREADS, 8)
diff_gated_topk_kernel(const float* __restrict__ x, float* __restrict__ out) {
    __shared__ unsigned hist[1024];          // 768 sub-bins + zero padding
    __shared__ unsigned candW[8 * SEG];      // per-warp window candidate segments
    __shared__ unsigned candT[8 * TSEG];     // per-warp top-2 candidate segments
    __shared__ unsigned cand2[32];
    __shared__ unsigned wctr[8], wctrT[8];
    __shared__ unsigned warp_off[8];
    __shared__ float    w_m1[8], w_m2[8];
    __shared__ unsigned s_cnthi, s_ncand2, s_bin2, s_want2;
    __shared__ float    s_thrf, s_gain;

    const int t    = threadIdx.x;
    const int lane = t & 31;
    const int warp = t >> 5;
    const unsigned lmask = (1u << lane) - 1u;
    const size_t base = (size_t)blockIdx.x * D;

    const float4* in4  = (const float4*)(x + base);
    float4*       out4 = (float4*)(out + base);
    uint4*        h4   = (uint4*)hist;

    // ---- P0: zero sub-bin hist ----
    h4[t] = make_uint4(0, 0, 0, 0);
    if (t == 0) { s_cnthi = 0; s_ncand2 = 0; }
    __syncthreads();

    // ---- P1: single row sweep, ZERO atomics: ballot-aggregated gathers ----
    unsigned cnt  = 0;       // elements >= WHI (exact rank offset)
    unsigned wcnt = 0;       // per-warp window counter (uniform register)
    unsigned tcnt = 0;       // per-warp top-2 counter  (uniform register)
#pragma unroll
    for (int i = 0; i < V4PT; i++) {
        float4 v = in4[t + i * THREADS];       // default caching: L1-resident for reuse
        float f[4] = {v.x, v.y, v.z, v.w};
#pragma unroll
        for (int c = 0; c < 4; c++) {
            const float fv = f[c];
            const bool inw = (fv >= WLO) && (fv < WHI);
            unsigned bal = __ballot_sync(FULL, inw);
            if (inw) {
                unsigned off = wcnt + __popc(bal & lmask);
                if (off < SEG) candW[(warp << 7) + off] = __float_as_uint(fv);
            }
            wcnt += __popc(bal);
            cnt += (fv >= WHI) ? 1u : 0u;
            const bool top = (fv >= TLO);
            unsigned balT = __ballot_sync(FULL, top);
            if (top) {
                unsigned off = tcnt + __popc(balT & lmask);
                if (off < TSEG) candT[(warp << 4) + off] = __float_as_uint(fv);
            }
            tcnt += __popc(balT);
        }
    }
    cnt = __reduce_add_sync(FULL, cnt);
    if (lane == 0) {
        wctr[warp]  = wcnt;
        wctrT[warp] = tcnt;
        atomicAdd(&s_cnthi, cnt);
    }
    __syncthreads();

    // ---- P2: uniform validity check ----
    bool of = false;
    unsigned nT = 0;
#pragma unroll
    for (int w = 0; w < 8; w++) {
        of |= (wctr[w] > SEG);
        unsigned d = wctrT[w]; of |= (d > TSEG); nT += (d > TSEG ? TSEG : d);
    }
    const unsigned ch = s_cnthi;
    unsigned ncW = 0;
#pragma unroll
    for (int w = 0; w < 8; w++) ncW += wctr[w];
    const bool slow = of || (nT < 2u) || (ch >= KSEL) || (ch + ncW < KSEL);

    if (!slow) {
        // ================= fast path =================
        const unsigned want0 = KSEL - ch;      // rank wanted inside the window

        // ---- P3: warp0 computes gain; all warps build 768-bin hist over candidates ----
        if (warp == 0) {
            float m1 = NEG_INF, m2 = NEG_INF;
#pragma unroll
            for (int s = 0; s < 4; s++) {
                int slot = lane + 32 * s;
                bool ok = (unsigned)(slot & 15) < wctrT[slot >> 4];
                float a = ok ? __uint_as_float(candT[slot]) : NEG_INF;
                float hi = fmaxf(m1, a);
                float lo = fminf(m1, a);
                m2 = fmaxf(m2, lo);
                m1 = hi;
            }
#pragma unroll
            for (int o = 16; o > 0; o >>= 1) {
                float a = __shfl_down_sync(FULL, m1, o);
                float b = __shfl_down_sync(FULL, m2, o);
                float hi = fmaxf(m1, a);
                float lo = fminf(m1, a);
                m2 = fmaxf(fmaxf(m2, b), lo);
                m1 = hi;
            }
            if (lane == 0) s_gain = GAIN / (1.0f + __expf(-(m1 - m2))) + 1.0f;
        }
#pragma unroll
        for (int k = 0; k < (8 * SEG) / THREADS; k++) {
            int ci = t + k * THREADS;
            if ((unsigned)(ci & (SEG - 1)) < wctr[ci >> 7]) {
                unsigned u = candW[ci];
                atomicAdd(&hist[(u - WLOBITS) >> 13], 1u);   // ~510 adds over 768 bins
            }
        }
        __syncthreads();

        // ---- P4: descending rank scan over 1024 bins (768 live) ----
        const int qb = 4 * (255 - t);          // t=0 owns the TOP bins
        const uint4 hv = h4[255 - t];
        unsigned h[4] = {hv.x, hv.y, hv.z, hv.w};
        unsigned csum = h[0] + h[1] + h[2] + h[3];
        unsigned inc = csum;
#pragma unroll
        for (int o = 1; o < 32; o <<= 1) {
            unsigned n = __shfl_up_sync(FULL, inc, o);
            if (lane >= o) inc += n;
        }
        if (lane == 31) warp_off[warp] = inc;
        __syncthreads();
        if (t == 0) {
            unsigned run = 0;
#pragma unroll
            for (int w = 0; w < 8; w++) {
                unsigned tt = warp_off[w];
                warp_off[w] = run;
                run += tt;
            }
        }
        __syncthreads();
        {
            const unsigned excl = warp_off[warp] + inc - csum;
            if (excl < want0 && want0 <= excl + csum) {   // exactly one thread
                unsigned cum = excl;
#pragma unroll
                for (int j = 3; j >= 0; j--) {
                    unsigned c = h[j];
                    if (cum + c >= want0) { s_bin2 = (unsigned)(qb + j); s_want2 = want0 - cum; break; }
                    cum += c;
                }
            }
        }
        __syncthreads();

        // ---- P5: collect sub-bin candidates (expected ~1) ----
        {
            const unsigned bin2 = s_bin2;
#pragma unroll
            for (int k = 0; k < (8 * SEG) / THREADS; k++) {
                int ci = t + k * THREADS;
                if ((unsigned)(ci & (SEG - 1)) < wctr[ci >> 7]) {
                    unsigned u = candW[ci];
                    if (((u - WLOBITS) >> 13) == bin2) {
                        unsigned p = atomicAdd(&s_ncand2, 1u);
                        if (p < 32) cand2[p] = u;
                    }
                }
            }
        }
        __syncthreads();

        // ---- P6: exact select among sub-bin candidates ----
        {
            unsigned nc2 = s_ncand2; if (nc2 > 32) nc2 = 32;
            const unsigned want2 = s_want2;
            if (t < (int)nc2) {
                unsigned v = cand2[t];
                unsigned gt = 0, eq = 0;
                for (unsigned j = 0; j < nc2; j++) {
                    unsigned u = cand2[j];
                    gt += (u > v);
                    eq += (u == v);
                }
                if (gt < want2 && gt + eq >= want2)
                    s_thrf = __uint_as_float(v);   // positive bits == value order
            }
        }
        __syncthreads();
    } else {
        // ================= exact generic slow path (~never taken) =================
        h4[t] = make_uint4(0, 0, 0, 0);
        if (t == 0) s_ncand2 = 0;
        __syncthreads();
        for (int i = 0; i < V4PT; i++) {
            float4 v = in4[t + i * THREADS];
            unsigned u[4] = {__float_as_uint(v.x), __float_as_uint(v.y),
                             __float_as_uint(v.z), __float_as_uint(v.w)};
            for (int c = 0; c < 4; c++)
                atomicAdd(&hist[f2s(u[c]) >> 22], 1u);
        }
        __syncthreads();
        if (t == 0) {
            unsigned cum = 0;
            for (int b = 1023; b >= 0; b--) {
                unsigned c = hist[b];
                if (cum + c >= KSEL) { s_bin2 = (unsigned)b; s_want2 = KSEL - cum; break; }
                cum += c;
            }
        }
        __syncthreads();
        // collect key-matching candidates + full top-2 reduce
        float m1 = NEG_INF, m2 = NEG_INF;
        const unsigned binS = s_bin2;
        for (int i = 0; i < V4PT; i++) {
            float4 v = in4[t + i * THREADS];
            float f[4] = {v.x, v.y, v.z, v.w};
            for (int c = 0; c < 4; c++) {
                float hi = fmaxf(m1, f[c]);
                float lo = fminf(m1, f[c]);
                m2 = fmaxf(m2, lo);
                m1 = hi;
                unsigned key = f2s(__float_as_uint(f[c]));
                if ((key >> 22) == binS) {
                    unsigned p = atomicAdd(&s_ncand2, 1u);
                    if (p < 8 * SEG) candW[p] = key;
                }
            }
        }
#pragma unroll
        for (int o = 16; o > 0; o >>= 1) {
            float a = __shfl_down_sync(FULL, m1, o);
            float b = __shfl_down_sync(FULL, m2, o);
            float hi = fmaxf(m1, a);
            float lo = fminf(m1, a);
            m2 = fmaxf(fmaxf(m2, b), lo);
            m1 = hi;
        }
        if (lane == 0) { w_m1[warp] = m1; w_m2[warp] = m2; }
        __syncthreads();
        if (t == 0) {
            float v1 = w_m1[0], v2 = w_m2[0];
#pragma unroll
            for (int w = 1; w < 8; w++) {
                float a = w_m1[w], b = w_m2[w];
                float hi = fmaxf(v1, a);
                float lo = fminf(v1, a);
                v2 = fmaxf(fmaxf(v2, b), lo);
                v1 = hi;
            }
            s_gain = GAIN / (1.0f + __expf(-(v1 - v2))) + 1.0f;
        }
        __syncthreads();
        {
            unsigned ncS = s_ncand2; if (ncS > 8 * SEG) ncS = 8 * SEG;
            const unsigned wantS = s_want2;
            for (unsigned ci = t; ci < ncS; ci += THREADS) {
                unsigned v = candW[ci];
                unsigned gt = 0, eq = 0;
                for (unsigned j = 0; j < ncS; j++) {
                    unsigned u = candW[j];
                    gt += (u > v);
                    eq += (u == v);
                }
                if (gt < wantS && gt + eq >= wantS) s_thrf = s2f(v);
            }
        }
        __syncthreads();
    }

    // ---- P7: re-read (L1-resident) + gated scaled write-out ----
    const float thr  = s_thrf;
    const float gain = s_gain;
#pragma unroll
    for (int i = 0; i < V4PT; i++) {
        float4 v = in4[t + i * THREADS];
        v.x = (v.x >= thr) ? v.x * gain : 0.0f;
        v.y = (v.y >= thr) ? v.y * gain : 0.0f;
        v.z = (v.z >= thr) ? v.z * gain : 0.0f;
        v.w = (v.w >= thr) ? v.w * gain : 0.0f;
        __stcs(&out4[t + i * THREADS], v);
    }
}

extern "C" void kernel_launch(void* const* d_in, const int* in_sizes, int n_in,
                              void* d_out, int out_size) {
    const float* x = (const float*)d_in[0];
    float* out = (float*)d_out;
    const int n_rows = in_sizes[0] / D;   // 16384
    diff_gated_topk_kernel<<<n_rows, THREADS>>>(x, out);
}

// round 16
// speedup vs baseline: 1.0812x; 1.0812x over previous
#include <cuda_runtime.h>
#include <math.h>

#define D        4096
#define KSEL     614              // int(4096 * 0.15)
#define THREADS  256
#define V4PT     4                // float4 per thread
#define SEG      192              // candidates per warp (lambda~98, ~10 sigma headroom)
#define NSLOT    (8 * SEG)        // 1536
#define WLOBITS  0x3F600000u      // bits of 0.875f  (k-th value = 1.036 +- 0.024)
#define WHIBITS  0x3FC00000u      // bits of 1.5f
#define SPANALL  0x40A00000u      // 0x80000000 - WLOBITS: u in [0.875, +inf) positive
#define FULL     0xFFFFFFFFu
#define GAIN     3.0f
#define NEG_INF  (-__int_as_float(0x7F800000))

// monotone float <-> uint mapping (slow path only)
__device__ __forceinline__ unsigned f2s(unsigned u) {
    return u ^ ((u & 0x80000000u) ? 0xFFFFFFFFu : 0x80000000u);
}
__device__ __forceinline__ float s2f(unsigned s) {
    unsigned u = (s & 0x80000000u) ? (s ^ 0x80000000u) : ~s;
    return __uint_as_float(u);
}

__global__ void __launch_bounds__(THREADS, 8)
diff_gated_topk_kernel(const float* __restrict__ x, float* __restrict__ out) {
    __shared__ unsigned hist[1024];          // 768 window sub-bins + padding
    __shared__ unsigned candW[NSLOT];        // per-warp segments of values >= 0.875
    __shared__ unsigned cand2[32];
    __shared__ unsigned wctr[8];
    __shared__ unsigned warp_off[8];
    __shared__ float    w_m1[8], w_m2[8];
    __shared__ unsigned s_cnthi, s_ncand2, s_bin2, s_want2;
    __shared__ float    s_thrf, s_gain;

    const int t    = threadIdx.x;
    const int lane = t & 31;
    const int warp = t >> 5;
    const unsigned lmask = (1u << lane) - 1u;
    const size_t base = (size_t)blockIdx.x * D;

    const float4* in4  = (const float4*)(x + base);
    float4*       out4 = (float4*)(out + base);
    uint4*        h4   = (uint4*)hist;

    // ---- P0: zero hist ----
    h4[t] = make_uint4(0, 0, 0, 0);
    if (t == 0) { s_cnthi = 0; s_ncand2 = 0; }
    __syncthreads();

    // ---- P1: single sweep, ONE test + ONE ballot + ONE gather per element ----
    unsigned wcnt = 0;
    const unsigned segbase = warp * SEG;
#pragma unroll
    for (int i = 0; i < V4PT; i++) {
        float4 v = in4[t + i * THREADS];      // default caching: L1-resident for reuse
        unsigned u[4] = {__float_as_uint(v.x), __float_as_uint(v.y),
                         __float_as_uint(v.z), __float_as_uint(v.w)};
#pragma unroll
        for (int c = 0; c < 4; c++) {
            const bool inw = (u[c] - WLOBITS) < SPANALL;   // positive && >= 0.875
            unsigned bal = __ballot_sync(FULL, inw);
            if (inw) {
                unsigned off = wcnt + __popc(bal & lmask);
                if (off < SEG) candW[segbase + off] = u[c];
            }
            wcnt += __popc(bal);
        }
    }
    if (lane == 0) wctr[warp] = wcnt;
    __syncthreads();

    // ---- P2: uniform validity ----
    bool of = false; unsigned ncW = 0;
#pragma unroll
    for (int w = 0; w < 8; w++) { unsigned c = wctr[w]; of |= (c > SEG); ncW += c; }
    bool slow = of || (ncW < KSEL);
    unsigned want0 = 0;

    if (!slow) {
        // ---- P3: each warp scans ITS OWN segment: top-2 + hi-count + window hist ----
        float m1 = NEG_INF, m2 = NEG_INF;
        unsigned chi = 0;
        for (unsigned idx = lane; idx < wcnt; idx += 32) {
            unsigned u = candW[segbase + idx];
            float f = __uint_as_float(u);
            float hi = fmaxf(m1, f);
            float lo = fminf(m1, f);
            m2 = fmaxf(m2, lo);
            m1 = hi;
            if (u >= WHIBITS) chi++;                           // above window: rank offset
            else atomicAdd(&hist[(u - WLOBITS) >> 13], 1u);    // window sub-bin
        }
#pragma unroll
        for (int o = 16; o > 0; o >>= 1) {
            float a = __shfl_down_sync(FULL, m1, o);
            float b = __shfl_down_sync(FULL, m2, o);
            float hi = fmaxf(m1, a);
            float lo = fminf(m1, a);
            m2 = fmaxf(fmaxf(m2, b), lo);
            m1 = hi;
        }
        chi = __reduce_add_sync(FULL, chi);
        if (lane == 0) { w_m1[warp] = m1; w_m2[warp] = m2; atomicAdd(&s_cnthi, chi); }
        __syncthreads();

        if (t == 0) {                          // exact global top-2 -> gain
            float v1 = w_m1[0], v2 = w_m2[0];
#pragma unroll
            for (int w = 1; w < 8; w++) {
                float a = w_m1[w], b = w_m2[w];
                float hi = fmaxf(v1, a);
                float lo = fminf(v1, a);
                v2 = fmaxf(fmaxf(v2, b), lo);
                v1 = hi;
            }
            s_gain = GAIN / (1.0f + __expf(-(v1 - v2))) + 1.0f;
        }
        const unsigned ch = s_cnthi;           // complete at the barrier above
        slow = (ch >= KSEL);                   // k-th above window: generic path
        want0 = KSEL - ch;

        if (!slow) {
            // ---- P4: descending rank scan over 1024 bins (768 live) ----
            const int qb = 4 * (255 - t);      // t=0 owns TOP bins
            const uint4 hv = h4[255 - t];
            unsigned h[4] = {hv.x, hv.y, hv.z, hv.w};
            unsigned csum = h[0] + h[1] + h[2] + h[3];
            unsigned inc = csum;
#pragma unroll
            for (int o = 1; o < 32; o <<= 1) {
                unsigned n = __shfl_up_sync(FULL, inc, o);
                if (lane >= o) inc += n;
            }
            if (lane == 31) warp_off[warp] = inc;
            __syncthreads();
            if (t == 0) {
                unsigned run = 0;
#pragma unroll
                for (int w = 0; w < 8; w++) {
                    unsigned tt = warp_off[w];
                    warp_off[w] = run;
                    run += tt;
                }
            }
            __syncthreads();
            {
                const unsigned excl = warp_off[warp] + inc - csum;
                if (excl < want0 && want0 <= excl + csum) {    // exactly one thread
                    unsigned cum = excl;
#pragma unroll
                    for (int j = 3; j >= 0; j--) {
                        unsigned c = h[j];
                        if (cum + c >= want0) { s_bin2 = (unsigned)(qb + j); s_want2 = want0 - cum; break; }
                        cum += c;
                    }
                }
            }
            __syncthreads();

            // ---- P5: per-warp segment scan for sub-bin matches (expected ~1) ----
            {
                const unsigned bin2 = s_bin2;
                for (unsigned idx = lane; idx < wcnt; idx += 32) {
                    unsigned u = candW[segbase + idx];
                    if (u < WHIBITS && ((u - WLOBITS) >> 13) == bin2) {
                        unsigned p = atomicAdd(&s_ncand2, 1u);
                        if (p < 32) cand2[p] = u;
                    }
                }
            }
            __syncthreads();

            // ---- P6: exact select among sub-bin candidates ----
            {
                unsigned nc2 = s_ncand2; if (nc2 > 32) nc2 = 32;
                const unsigned want2 = s_want2;
                if (t < (int)nc2) {
                    unsigned v = cand2[t];
                    unsigned gt = 0, eq = 0;
                    for (unsigned j = 0; j < nc2; j++) {
                        unsigned u = cand2[j];
                        gt += (u > v);
                        eq += (u == v);
                    }
                    if (gt < want2 && gt + eq >= want2)
                        s_thrf = __uint_as_float(v);   // positive bits == value order
                }
            }
            __syncthreads();
        }
    }

    if (slow) {
        // ================= exact generic slow path (~never taken) =================
        __syncthreads();
        h4[t] = make_uint4(0, 0, 0, 0);
        if (t == 0) s_ncand2 = 0;
        __syncthreads();
        for (int i = 0; i < V4PT; i++) {
            float4 v = in4[t + i * THREADS];
            unsigned u[4] = {__float_as_uint(v.x), __float_as_uint(v.y),
                             __float_as_uint(v.z), __float_as_uint(v.w)};
            for (int c = 0; c < 4; c++)
                atomicAdd(&hist[f2s(u[c]) >> 22], 1u);
        }
        __syncthreads();
        if (t == 0) {
            unsigned cum = 0;
            for (int b = 1023; b >= 0; b--) {
                unsigned c = hist[b];
                if (cum + c >= KSEL) { s_bin2 = (unsigned)b; s_want2 = KSEL - cum; break; }
                cum += c;
            }
        }
        __syncthreads();
        // collect key-matching candidates + full top-2 reduce
        float m1 = NEG_INF, m2 = NEG_INF;
        const unsigned binS = s_bin2;
        for (int i = 0; i < V4PT; i++) {
            float4 v = in4[t + i * THREADS];
            float f[4] = {v.x, v.y, v.z, v.w};
            for (int c = 0; c < 4; c++) {
                float hi = fmaxf(m1, f[c]);
                float lo = fminf(m1, f[c]);
                m2 = fmaxf(m2, lo);
                m1 = hi;
                unsigned key = f2s(__float_as_uint(f[c]));
                if ((key >> 22) == binS) {
                    unsigned p = atomicAdd(&s_ncand2, 1u);
                    if (p < NSLOT) candW[p] = key;
                }
            }
        }
#pragma unroll
        for (int o = 16; o > 0; o >>= 1) {
            float a = __shfl_down_sync(FULL, m1, o);
            float b = __shfl_down_sync(FULL, m2, o);
            float hi = fmaxf(m1, a);
            float lo = fminf(m1, a);
            m2 = fmaxf(fmaxf(m2, b), lo);
            m1 = hi;
        }
        if (lane == 0) { w_m1[warp] = m1; w_m2[warp] = m2; }
        __syncthreads();
        if (t == 0) {
            float v1 = w_m1[0], v2 = w_m2[0];
#pragma unroll
            for (int w = 1; w < 8; w++) {
                float a = w_m1[w], b = w_m2[w];
                float hi = fmaxf(v1, a);
                float lo = fminf(v1, a);
                v2 = fmaxf(fmaxf(v2, b), lo);
                v1 = hi;
            }
            s_gain = GAIN / (1.0f + __expf(-(v1 - v2))) + 1.0f;
        }
        __syncthreads();
        {
            unsigned ncS = s_ncand2; if (ncS > NSLOT) ncS = NSLOT;
            const unsigned wantS = s_want2;
            for (unsigned ci = t; ci < ncS; ci += THREADS) {
                unsigned v = candW[ci];
                unsigned gt = 0, eq = 0;
                for (unsigned j = 0; j < ncS; j++) {
                    unsigned u = candW[j];
                    gt += (u > v);
                    eq += (u == v);
                }
                if (gt < wantS && gt + eq >= wantS) s_thrf = s2f(v);
            }
        }
        __syncthreads();
    }

    // ---- P7: re-read (L1-resident) + gated scaled write-out ----
    const float thr  = s_thrf;
    const float gain = s_gain;
#pragma unroll
    for (int i = 0; i < V4PT; i++) {
        float4 v = in4[t + i * THREADS];
        v.x = (v.x >= thr) ? v.x * gain : 0.0f;
        v.y = (v.y >= thr) ? v.y * gain : 0.0f;
        v.z = (v.z >= thr) ? v.z * gain : 0.0f;
        v.w = (v.w >= thr) ? v.w * gain : 0.0f;
        __stcs(&out4[t + i * THREADS], v);
    }
}

extern "C" void kernel_launch(void* const* d_in, const int* in_sizes, int n_in,
                              void* d_out, int out_size) {
    const float* x = (const float*)d_in[0];
    float* out = (float*)d_out;
    const int n_rows = in_sizes[0] / D;   // 16384
    diff_gated_topk_kernel<<<n_rows, THREADS>>>(x, out);
}